// round 1
// baseline (speedup 1.0000x reference)
#include <cuda_runtime.h>
#include <cstdint>
#include <cstdio>

#define S 2048
#define Dm 2048
#define Hh 16
#define HD 128
#define CACHE 408
#define RECENT 204
#define PENALTY 0.4f
#define NEG_MIN_F (-3.4028234663852886e38f)
#define SQRT_HD_F 11.313708498984761f

// ---------------- scratch (device globals; no allocation allowed) ----------------
__device__ float g_Q[Hh * S * HD];            // [h][s][d]
__device__ float g_K[Hh * S * HD];
__device__ float g_V[Hh * S * HD];
__device__ float g_scores[Hh * S * S];        // unnormalized exp(logit - rowmax); 256MB
__device__ float g_rownorm[Hh * S];           // full-row sum of exp (true softmax norm)
__device__ float g_rowsum[Hh * S];            // sum of kept (non-evicted) exp per row
__device__ int   g_evict[Hh * S];             // step at which pos was evicted (INT_MAX if never)
__device__ float g_attnout[S * Dm];           // [s][h*HD+d]

// ---------------- generic NT GEMM: C = A * B^T, both row-major K-contiguous ------
// MODE 0: plain C[m*N+n]
// MODE 1: QKV split-head output C[((n>>7)*S + m)*HD + (n&127)]
// MODE 2: logits epilogue: v/sqrt(HD) + mask[m*S+n], clamp, plain store
template <int MODE>
__global__ void __launch_bounds__(256, 2) gemm_nt_kernel(
    const float* __restrict__ A, const float* __restrict__ B, float* __restrict__ C,
    int M, int N, int Kd, size_t az, size_t bz, size_t cz,
    const float* __restrict__ maskAdd, int causalSkip)
{
    int m0 = blockIdx.y * 128, n0 = blockIdx.x * 128;
    if (causalSkip && n0 > m0) return;   // strictly upper tiles never read downstream
    const float* Ab = A + (size_t)blockIdx.z * az;
    const float* Bb = B + (size_t)blockIdx.z * bz;
    float*       Cb = C + (size_t)blockIdx.z * cz;

    __shared__ float As[8][132];
    __shared__ float Bs[8][132];
    int tid = threadIdx.x;
    int tx = tid & 15, ty = tid >> 4;
    int lrow = tid >> 1, lcol = (tid & 1) * 4;

    float acc[8][8];
#pragma unroll
    for (int i = 0; i < 8; i++)
#pragma unroll
        for (int j = 0; j < 8; j++) acc[i][j] = 0.f;

    const float* aPtr = Ab + (size_t)(m0 + lrow) * Kd + lcol;
    const float* bPtr = Bb + (size_t)(n0 + lrow) * Kd + lcol;

    for (int k0 = 0; k0 < Kd; k0 += 8) {
        float4 av = *(const float4*)(aPtr + k0);
        float4 bv = *(const float4*)(bPtr + k0);
        As[lcol + 0][lrow] = av.x; As[lcol + 1][lrow] = av.y;
        As[lcol + 2][lrow] = av.z; As[lcol + 3][lrow] = av.w;
        Bs[lcol + 0][lrow] = bv.x; Bs[lcol + 1][lrow] = bv.y;
        Bs[lcol + 2][lrow] = bv.z; Bs[lcol + 3][lrow] = bv.w;
        __syncthreads();
#pragma unroll
        for (int kk = 0; kk < 8; kk++) {
            float a[8], b[8];
            *(float4*)&a[0] = *(const float4*)&As[kk][ty * 8];
            *(float4*)&a[4] = *(const float4*)&As[kk][ty * 8 + 4];
            *(float4*)&b[0] = *(const float4*)&Bs[kk][tx * 8];
            *(float4*)&b[4] = *(const float4*)&Bs[kk][tx * 8 + 4];
#pragma unroll
            for (int i = 0; i < 8; i++)
#pragma unroll
                for (int j = 0; j < 8; j++)
                    acc[i][j] = fmaf(a[i], b[j], acc[i][j]);
        }
        __syncthreads();
    }

#pragma unroll
    for (int i = 0; i < 8; i++) {
        int m = m0 + ty * 8 + i;
#pragma unroll
        for (int j = 0; j < 8; j++) {
            int n = n0 + tx * 8 + j;
            float v = acc[i][j];
            if (MODE == 2) {
                v = v / SQRT_HD_F;
                v = fmaxf(v + maskAdd[(size_t)m * S + n], NEG_MIN_F);
                Cb[(size_t)m * N + n] = v;
            } else if (MODE == 1) {
                Cb[(((size_t)(n >> 7)) * S + m) * HD + (n & 127)] = v;
            } else {
                Cb[(size_t)m * N + n] = v;
            }
        }
    }
}

// ---------------- RoPE (in place on g_Q, g_K) ----------------
__global__ void __launch_bounds__(64) rope_kernel(const int* __restrict__ pos_ids)
{
    int hs = blockIdx.x;
    int h = hs / S, s = hs % S;
    int d = threadIdx.x;                       // 0..63
    float posf = (float)pos_ids[s];
    float invf = powf(10000.f, -((float)d) / 64.f);
    float fr = posf * invf;
    float c = cosf(fr), sn = sinf(fr);
    size_t base = ((size_t)h * S + s) * HD;
    float q1 = g_Q[base + d], q2 = g_Q[base + d + 64];
    g_Q[base + d]      = q1 * c - q2 * sn;
    g_Q[base + d + 64] = q2 * c + q1 * sn;
    float k1 = g_K[base + d], k2 = g_K[base + d + 64];
    g_K[base + d]      = k1 * c - k2 * sn;
    g_K[base + d + 64] = k2 * c + k1 * sn;
}

// ---------------- row softmax -> unnormalized exp + rownorm ----------------
__global__ void __launch_bounds__(256) softmax_kernel()
{
    int r = blockIdx.x, h = blockIdx.y, tid = threadIdx.x;
    float* row = g_scores + ((size_t)h * S + r) * S;
    int n = r + 1;
    __shared__ float sred[9];

    float v[8];
    float mx = NEG_MIN_F;
#pragma unroll
    for (int i = 0; i < 8; i++) {
        int p = tid + i * 256;
        v[i] = (p < n) ? row[p] : NEG_MIN_F;
        mx = fmaxf(mx, v[i]);
    }
#pragma unroll
    for (int o = 16; o > 0; o >>= 1) mx = fmaxf(mx, __shfl_xor_sync(0xffffffffu, mx, o));
    if ((tid & 31) == 0) sred[tid >> 5] = mx;
    __syncthreads();
    if (tid == 0) { float m = sred[0]; for (int i = 1; i < 8; i++) m = fmaxf(m, sred[i]); sred[8] = m; }
    __syncthreads();
    mx = sred[8];
    __syncthreads();

    float e[8], loc = 0.f;
#pragma unroll
    for (int i = 0; i < 8; i++) {
        int p = tid + i * 256;
        e[i] = (p < n) ? __expf(v[i] - mx) : 0.f;
        loc += e[i];
    }
#pragma unroll
    for (int o = 16; o > 0; o >>= 1) loc += __shfl_xor_sync(0xffffffffu, loc, o);
    if ((tid & 31) == 0) sred[tid >> 5] = loc;
    __syncthreads();
    if (tid == 0) { float s2 = 0.f; for (int i = 0; i < 8; i++) s2 += sred[i]; g_rownorm[h * S + r] = s2; }

#pragma unroll
    for (int i = 0; i < 8; i++) { int p = tid + i * 256; row[p] = e[i]; }  // zeros beyond r stay zero
}

// ---------------- evict-step init ----------------
__global__ void evinit_kernel()
{
    int i = blockIdx.x * 256 + threadIdx.x;
    if (i < Hh * S) g_evict[i] = 0x7fffffff;
}

// ---------------- the sequential greedy-eviction scan: one CTA per head ----------------
__global__ void __launch_bounds__(256) scan_kernel()
{
    int h = blockIdx.x, tid = threadIdx.x;
    const float* sc = g_scores + (size_t)h * S * S;
    __shared__ float coefEff[CACHE];
    __shared__ float sredf[9];
    __shared__ unsigned long long sredu[9];

    // warm-up coefficients: P^(cache-1-i) / rownorm[i]  (underflows to 0 for old rows)
    for (int i = tid; i < CACHE; i += 256) {
        float cf = powf(PENALTY, (float)(CACHE - 1 - i));
        coefEff[i] = cf / g_rownorm[h * S + i];
    }
    __syncthreads();

    float sel[8];
#pragma unroll
    for (int i = 0; i < 8; i++) sel[i] = 0.f;

    for (int rrow = 0; rrow < CACHE; rrow++) {
        float cf = coefEff[rrow];
        if (cf > 0.f) {
            const float* rp = sc + (size_t)rrow * S + tid;
#pragma unroll
            for (int i = 0; i < 8; i++) sel[i] = fmaf(cf, rp[i * 256], sel[i]);
        }
    }

    // prefetch first scan row
    float nr[8];
    {
        const float* rp = sc + (size_t)CACHE * S + tid;
#pragma unroll
        for (int i = 0; i < 8; i++) nr[i] = rp[i * 256];
    }

    for (int t = CACHE; t < S - 1; t++) {
        float r[8];
#pragma unroll
        for (int i = 0; i < 8; i++) r[i] = nr[i];
        // issue next-row loads early (hides DRAM latency behind the reductions)
        if (t + 1 < S - 1) {
            const float* rp = sc + (size_t)(t + 1) * S + tid;
#pragma unroll
            for (int i = 0; i < 8; i++) nr[i] = rp[i * 256];
        }

        float c[8], loc = 0.f;
#pragma unroll
        for (int i = 0; i < 8; i++) {
            c[i] = (sel[i] <= 1.0e30f) ? r[i] : 0.f;   // evicted -> select=inf -> contributes 0
            loc += c[i];
        }
#pragma unroll
        for (int o = 16; o > 0; o >>= 1) loc += __shfl_xor_sync(0xffffffffu, loc, o);
        if ((tid & 31) == 0) sredf[tid >> 5] = loc;
        __syncthreads();
        if (tid == 0) { float s2 = 0.f; for (int i = 0; i < 8; i++) s2 += sredf[i]; sredf[8] = s2; }
        __syncthreads();
        float tot = sredf[8];

        int lim = t - RECENT;
        unsigned long long key = ~0ull;
#pragma unroll
        for (int i = 0; i < 8; i++) {
            float ns = __fadd_rn(__fmul_rn(PENALTY, sel[i]), __fdiv_rn(c[i], tot));
            sel[i] = ns;
            int p = tid + i * 256;
            if (p <= lim) {
                unsigned long long k2 =
                    ((unsigned long long)__float_as_uint(ns) << 32) | (unsigned int)p;
                if (k2 < key) key = k2;       // nonneg floats: bit order == value order; low idx wins ties
            }
        }
#pragma unroll
        for (int o = 16; o > 0; o >>= 1) {
            unsigned long long ok = __shfl_xor_sync(0xffffffffu, key, o);
            if (ok < key) key = ok;
        }
        if ((tid & 31) == 0) sredu[tid >> 5] = key;
        __syncthreads();
        if (tid == 0) {
            unsigned long long m2 = sredu[0];
            for (int i = 1; i < 8; i++) if (sredu[i] < m2) m2 = sredu[i];
            sredu[8] = m2;
        }
        __syncthreads();
        int mpos = (int)(sredu[8] & 0xffffffffu);

        if ((mpos & 255) == tid) {
            sel[mpos >> 8] = __int_as_float(0x7f800000);  // +inf
            g_evict[h * S + mpos] = t;
        }
    }
}

// ---------------- per-row kept-mass sums ----------------
__global__ void __launch_bounds__(256) rowsum_kernel()
{
    int r = blockIdx.x, h = blockIdx.y, tid = threadIdx.x;
    const float* row = g_scores + ((size_t)h * S + r) * S;
    const int* ev = g_evict + h * S;
    __shared__ float sred[9];
    float loc = 0.f;
    int n = r + 1;
    for (int p = tid; p < n; p += 256) loc += (ev[p] >= r) ? row[p] : 0.f;
#pragma unroll
    for (int o = 16; o > 0; o >>= 1) loc += __shfl_xor_sync(0xffffffffu, loc, o);
    if ((tid & 31) == 0) sred[tid >> 5] = loc;
    __syncthreads();
    if (tid == 0) { float s2 = 0.f; for (int i = 0; i < 8; i++) s2 += sred[i]; g_rowsum[h * S + r] = s2; }
}

// ---------------- PV: out[s, h*HD+d] = sum_j scores*keep*V / rowsum (NN GEMM) ----------------
__global__ void __launch_bounds__(256, 2) pv_kernel()
{
    int h = blockIdx.z;
    int m0 = blockIdx.x * 128;
    const float* Ab = g_scores + (size_t)h * S * S;
    const float* Bb = g_V + (size_t)h * S * HD;
    const int* ev = g_evict + h * S;
    __shared__ float As[8][132];
    __shared__ float Bs[8][132];
    int tid = threadIdx.x, tx = tid & 15, ty = tid >> 4;
    int lrow = tid >> 1, lcol = (tid & 1) * 4;
    int bk = tid >> 5, bc = (tid & 31) * 4;

    float acc[8][8];
#pragma unroll
    for (int i = 0; i < 8; i++)
#pragma unroll
        for (int j = 0; j < 8; j++) acc[i][j] = 0.f;

    int r = m0 + lrow;
    int kmax = m0 + 128;   // causal: scores zero beyond the diagonal block
    for (int k0 = 0; k0 < kmax; k0 += 8) {
        float4 av = *(const float4*)(Ab + (size_t)r * S + k0 + lcol);
        int kb = k0 + lcol;
        av.x = (ev[kb + 0] >= r) ? av.x : 0.f;
        av.y = (ev[kb + 1] >= r) ? av.y : 0.f;
        av.z = (ev[kb + 2] >= r) ? av.z : 0.f;
        av.w = (ev[kb + 3] >= r) ? av.w : 0.f;
        float4 bv = *(const float4*)(Bb + (size_t)(k0 + bk) * HD + bc);
        As[lcol + 0][lrow] = av.x; As[lcol + 1][lrow] = av.y;
        As[lcol + 2][lrow] = av.z; As[lcol + 3][lrow] = av.w;
        *(float4*)&Bs[bk][bc] = bv;
        __syncthreads();
#pragma unroll
        for (int kk = 0; kk < 8; kk++) {
            float a[8], b[8];
            *(float4*)&a[0] = *(const float4*)&As[kk][ty * 8];
            *(float4*)&a[4] = *(const float4*)&As[kk][ty * 8 + 4];
            *(float4*)&b[0] = *(const float4*)&Bs[kk][tx * 8];
            *(float4*)&b[4] = *(const float4*)&Bs[kk][tx * 8 + 4];
#pragma unroll
            for (int i = 0; i < 8; i++)
#pragma unroll
                for (int j = 0; j < 8; j++)
                    acc[i][j] = fmaf(a[i], b[j], acc[i][j]);
        }
        __syncthreads();
    }

#pragma unroll
    for (int i = 0; i < 8; i++) {
        int m = m0 + ty * 8 + i;
        float sden = g_rowsum[h * S + m];
#pragma unroll
        for (int j = 0; j < 8; j++) {
            g_attnout[(size_t)m * Dm + h * HD + tx * 8 + j] = acc[i][j] / sden;
        }
    }
}

// ---------------- launch ----------------
extern "C" void kernel_launch(void* const* d_in, const int* in_sizes, int n_in,
                              void* d_out, int out_size)
{
    (void)in_sizes; (void)n_in; (void)out_size;
    const float* hs    = (const float*)d_in[0];
    const float* amask = (const float*)d_in[1];
    const int*   pos   = (const int*)d_in[2];
    const float* wq    = (const float*)d_in[3];
    const float* wk    = (const float*)d_in[4];
    const float* wv    = (const float*)d_in[5];
    const float* wo    = (const float*)d_in[6];
    float* out = (float*)d_out;

    float *pQ, *pK, *pV, *pS, *pAO;
    cudaGetSymbolAddress((void**)&pQ,  g_Q);
    cudaGetSymbolAddress((void**)&pK,  g_K);
    cudaGetSymbolAddress((void**)&pV,  g_V);
    cudaGetSymbolAddress((void**)&pS,  g_scores);
    cudaGetSymbolAddress((void**)&pAO, g_attnout);

    dim3 thr(256);
    // QKV projections, split-head layout
    gemm_nt_kernel<1><<<dim3(16, 16, 1), thr>>>(hs, wq, pQ, S, Dm, Dm, 0, 0, 0, nullptr, 0);
    gemm_nt_kernel<1><<<dim3(16, 16, 1), thr>>>(hs, wk, pK, S, Dm, Dm, 0, 0, 0, nullptr, 0);
    gemm_nt_kernel<1><<<dim3(16, 16, 1), thr>>>(hs, wv, pV, S, Dm, Dm, 0, 0, 0, nullptr, 0);
    // RoPE on Q,K
    rope_kernel<<<Hh * S, 64>>>(pos);
    // per-head logits (causal-skipped), masked + clamped
    gemm_nt_kernel<2><<<dim3(16, 16, Hh), thr>>>(pQ, pK, pS, S, S, HD,
                                                 (size_t)S * HD, (size_t)S * HD, (size_t)S * S,
                                                 amask, 1);
    // unnormalized exp + row norms
    softmax_kernel<<<dim3(S, Hh), thr>>>();
    // eviction scan
    evinit_kernel<<<(Hh * S + 255) / 256, 256>>>();
    scan_kernel<<<Hh, 256>>>();
    // kept-mass rowsums, then masked PV with renormalization
    rowsum_kernel<<<dim3(S, Hh), thr>>>();
    pv_kernel<<<dim3(16, 1, Hh), thr>>>();
    // output projection
    gemm_nt_kernel<0><<<dim3(16, 16, 1), thr>>>(pAO, wo, out, S, Dm, Dm, 0, 0, 0, nullptr, 0);
}